// round 10
// baseline (speedup 1.0000x reference)
#include <cuda_runtime.h>

#define Bsz   128
#define Lseq  4096
#define Hd    64
#define G3    192
#define IN2H  128
#define NCLS  230
#define BL    (Bsz * Lseq)

typedef unsigned long long ull;

// Scratch (allocation-free rule: __device__ globals)
__device__ float g_gx[(size_t)2 * BL * G3];    // [dir][b][t][192]  (~805 MB)
__device__ float g_buf[(size_t)BL * IN2H];     // [b][t][128]       (~268 MB)

// ---------------- packed f32x2 / fast-math helpers ----------------
__device__ __forceinline__ ull fma2(ull a, ull b, ull c) {
    ull d;
    asm("fma.rn.f32x2 %0, %1, %2, %3;" : "=l"(d) : "l"(a), "l"(b), "l"(c));
    return d;
}
__device__ __forceinline__ float2 u2f2(ull v) {
    float2 f;
    asm("mov.b64 {%0, %1}, %2;" : "=f"(f.x), "=f"(f.y) : "l"(v));
    return f;
}
__device__ __forceinline__ float tanh_fast(float x) {
    float y;
    asm("tanh.approx.f32 %0, %1;" : "=f"(y) : "f"(x));
    return y;
}
__device__ __forceinline__ float sigm_fast(float x) {
    return fmaf(0.5f, tanh_fast(0.5f * x), 0.5f);
}
__device__ __forceinline__ unsigned smem_u32(const void* p) {
    return (unsigned)__cvta_generic_to_shared(p);
}
__device__ __forceinline__ void cp_async8(unsigned dst, const void* src) {
    asm volatile("cp.async.ca.shared.global [%0], [%1], 8;"
                 :: "r"(dst), "l"(src));
}
__device__ __forceinline__ void cp_commit() {
    asm volatile("cp.async.commit_group;");
}
template <int N>
__device__ __forceinline__ void cp_wait() {
    asm volatile("cp.async.wait_group %0;" :: "n"(N));
}

// ---------------- gx GEMM for layers 1..3 (frozen R7 version) -------------
__global__ void __launch_bounds__(256, 2)
gx_gemm_kernel(const float* __restrict__ w_ih,
               const float* __restrict__ b_ih,
               int layer) {
    const int d  = blockIdx.x & 1;
    const int c0 = (blockIdx.x >> 1) * 96;       // column half
    const size_t row0 = (size_t)blockIdx.y * 64;
    const int tid = threadIdx.x;
    const int tx = tid & 15;   // cols c0 + tx + 16*j, j<6
    const int ty = tid >> 4;   // rows ty + 16*i, i<4

    const ull* inp2 = (const ull*)g_buf;  // 64 ull per row
    const ull* w2g =
        (const ull*)(w_ih + ((size_t)(layer - 1) * 2 + d) * G3 * IN2H);

    __shared__ ull a_s[2][16][65];   // [buf][kpair][row]
    __shared__ ull b_s[2][16][97];   // [buf][kpair][col]
    const unsigned A_BUF_BYTES = 16 * 65 * 8;
    const unsigned B_BUF_BYTES = 16 * 97 * 8;

    unsigned a_dst[4], b_dst[6];
    const ull* a_src[4];
    const ull* b_src[6];
#pragma unroll
    for (int it = 0; it < 4; it++) {
        int lin = tid + it * 256;
        int r = lin >> 4, c2 = lin & 15;
        a_dst[it] = smem_u32(&a_s[0][c2][r]);
        a_src[it] = inp2 + (row0 + r) * 64 + c2;
    }
#pragma unroll
    for (int it = 0; it < 6; it++) {
        int lin = tid + it * 256;
        int cc = lin >> 4, c2 = lin & 15;
        b_dst[it] = smem_u32(&b_s[0][c2][cc]);
        b_src[it] = w2g + (size_t)(c0 + cc) * 64 + c2;
    }

    ull acc[4][6];
#pragma unroll
    for (int i = 0; i < 4; i++)
#pragma unroll
        for (int j = 0; j < 6; j++) acc[i][j] = 0ULL;

#pragma unroll
    for (int it = 0; it < 4; it++) cp_async8(a_dst[it], a_src[it]);
#pragma unroll
    for (int it = 0; it < 6; it++) cp_async8(b_dst[it], b_src[it]);
    cp_commit();

#pragma unroll
    for (int ch = 0; ch < 4; ch++) {
        const int buf = ch & 1;
        if (ch < 3) {
            const int nb = (ch + 1) & 1;
#pragma unroll
            for (int it = 0; it < 4; it++)
                cp_async8(a_dst[it] + nb * A_BUF_BYTES,
                          a_src[it] + (ch + 1) * 16);
#pragma unroll
            for (int it = 0; it < 6; it++)
                cp_async8(b_dst[it] + nb * B_BUF_BYTES,
                          b_src[it] + (ch + 1) * 16);
            cp_commit();
            cp_wait<1>();
        } else {
            cp_wait<0>();
        }
        __syncthreads();
#pragma unroll
        for (int kp = 0; kp < 16; kp++) {
            ull a2[4], b2[6];
#pragma unroll
            for (int i = 0; i < 4; i++) a2[i] = a_s[buf][kp][ty + 16 * i];
#pragma unroll
            for (int j = 0; j < 6; j++) b2[j] = b_s[buf][kp][tx + 16 * j];
#pragma unroll
            for (int i = 0; i < 4; i++)
#pragma unroll
                for (int j = 0; j < 6; j++)
                    acc[i][j] = fma2(a2[i], b2[j], acc[i][j]);
        }
        __syncthreads();
    }

    const float* bih = b_ih + ((size_t)layer * 2 + d) * G3;
#pragma unroll
    for (int i = 0; i < 4; i++) {
        size_t row = row0 + ty + 16 * i;
#pragma unroll
        for (int j = 0; j < 6; j++) {
            int c = c0 + tx + 16 * j;
            float2 f = u2f2(acc[i][j]);
            g_gx[((size_t)d * BL + row) * G3 + c] = f.x + f.y + bih[c];
        }
    }
}

// ---------------- sequential GRU scan (split-k + shuffle) ----------------
// One block per batch element, 256 threads. tid = d*128 + j*2 + half:
//   d    = direction (two independent 128-thread groups, named barriers)
//   j    = h-component 0..63
//   half = which 32-wide k-half of the dots this thread computes
// Each thread computes ALL THREE gate dots (r,z,n) for component j over its
// k-half (weights: 3x16 ull = 96 regs). Halves combine via shfl_xor(1)
// (partners are adjacent lanes). Gates + h update on half==0 threads.
// Ping-pong h buffer -> ONE 128-thread barrier per step per direction.
__global__ void __launch_bounds__(256)
scan_kernel(const float* __restrict__ w_hh,
            const float* __restrict__ b_hh,
            const float* __restrict__ x,
            const float* __restrict__ w_ih0,
            const float* __restrict__ b_ih,
            int layer) {
    const int b = blockIdx.x;
    const int tid = threadIdx.x;
    const int d = tid >> 7;            // direction
    const int j = (tid & 127) >> 1;    // component
    const int half = tid & 1;          // k-half
    const unsigned barid = 1 + d;

    const size_t base = ((size_t)layer * 2 + d) * G3;
    const ull* Wr = (const ull*)w_hh + (base + j) * 32 + half * 16;
    const ull* Wz = (const ull*)w_hh + (base + 64 + j) * 32 + half * 16;
    const ull* Wn = (const ull*)w_hh + (base + 128 + j) * 32 + half * 16;
    ull wr[16], wz[16], wn[16];
#pragma unroll
    for (int i = 0; i < 16; i++) { wr[i] = Wr[i]; wz[i] = Wz[i]; wn[i] = Wn[i]; }
    const float br = b_hh[base + j];
    const float bz = b_hh[base + 64 + j];
    const float bn = b_hh[base + 128 + j];

    __shared__ __align__(16) float h_s[2][2][Hd];  // [dir][parity][comp]
    if ((tid & 127) < Hd) h_s[d][0][tid & 127] = 0.0f;
    float hreg = 0.0f;  // previous h[j], maintained on half==0

    const int t0 = (d == 0) ? 0 : (Lseq - 1);
    const int tstep = (d == 0) ? 1 : -1;
    const long gstep = (long)tstep * G3;

    // gx feed — only half==0 threads need it
    float w0r = 0.f, w0z = 0.f, w0n = 0.f, c0r = 0.f, c0z = 0.f, c0n = 0.f;
    const float* xs = nullptr;
    const float* gp = nullptr;
    if (layer == 0) {
        w0r = w_ih0[d * G3 + j];
        w0z = w_ih0[d * G3 + 64 + j];
        w0n = w_ih0[d * G3 + 128 + j];
        c0r = b_ih[(size_t)d * G3 + j];
        c0z = b_ih[(size_t)d * G3 + 64 + j];
        c0n = b_ih[(size_t)d * G3 + 128 + j];
        xs = x + (size_t)b * Lseq + t0;
    } else {
        gp = g_gx + (((size_t)d * Bsz + b) * Lseq + t0) * G3 + j;
    }
    float* outp = g_buf + (size_t)b * Lseq * IN2H + d * Hd + j;

    asm volatile("bar.sync %0, %1;" :: "r"(barid), "r"(128) : "memory");

    // depth-2 prefetch (half==0 only; half==1 regs stay dead)
    float qr[2], qz[2], qn[2];
#pragma unroll
    for (int p = 0; p < 2; p++) {
        if (half == 0) {
            if (layer == 0) {
                qr[p] = xs[(long)p * tstep]; qz[p] = 0.f; qn[p] = 0.f;
            } else {
                qr[p] = gp[(long)p * gstep];
                qz[p] = gp[(long)p * gstep + 64];
                qn[p] = gp[(long)p * gstep + 128];
            }
        }
    }

#pragma unroll 1
    for (int s = 0; s < Lseq; s++) {
        const int pr = s & 1;
        float rawr = qr[pr], rawz = qz[pr], rawn = qn[pr];
        const int sp = s + 2;
        if (half == 0 && sp < Lseq) {
            if (layer == 0) {
                qr[pr] = xs[(long)sp * tstep];
            } else {
                qr[pr] = gp[(long)sp * gstep];
                qz[pr] = gp[(long)sp * gstep + 64];
                qn[pr] = gp[(long)sp * gstep + 128];
            }
        }

        // half-dots for r,z,n over this thread's 32 h-components
        const ulonglong2* h4 =
            (const ulonglong2*)(h_s[d][pr] + half * 32);
        ull r0 = 0, r1 = 0, z0 = 0, z1 = 0, n0 = 0, n1 = 0;
#pragma unroll
        for (int i = 0; i < 4; i++) {
            ulonglong2 u = h4[2 * i];
            ulonglong2 v = h4[2 * i + 1];
            r0 = fma2(wr[4 * i + 0], u.x, r0);
            r1 = fma2(wr[4 * i + 1], u.y, r1);
            z0 = fma2(wz[4 * i + 0], u.x, z0);
            z1 = fma2(wz[4 * i + 1], u.y, z1);
            n0 = fma2(wn[4 * i + 0], u.x, n0);
            n1 = fma2(wn[4 * i + 1], u.y, n1);
            r0 = fma2(wr[4 * i + 2], v.x, r0);
            r1 = fma2(wr[4 * i + 3], v.y, r1);
            z0 = fma2(wz[4 * i + 2], v.x, z0);
            z1 = fma2(wz[4 * i + 3], v.y, z1);
            n0 = fma2(wn[4 * i + 2], v.x, n0);
            n1 = fma2(wn[4 * i + 3], v.y, n1);
        }
        float2 fr0 = u2f2(r0), fr1 = u2f2(r1);
        float2 fz0 = u2f2(z0), fz1 = u2f2(z1);
        float2 fn0 = u2f2(n0), fn1 = u2f2(n1);
        float pgr = (fr0.x + fr0.y) + (fr1.x + fr1.y);
        float pgz = (fz0.x + fz0.y) + (fz1.x + fz1.y);
        float pgn = (fn0.x + fn0.y) + (fn1.x + fn1.y);

        // combine halves: partner is adjacent lane
        pgr += __shfl_xor_sync(0xFFFFFFFFu, pgr, 1);
        pgz += __shfl_xor_sync(0xFFFFFFFFu, pgz, 1);
        pgn += __shfl_xor_sync(0xFFFFFFFFu, pgn, 1);

        if (half == 0) {
            float gxr, gxz, gxn;
            if (layer == 0) {
                gxr = fmaf(rawr, w0r, c0r);
                gxz = fmaf(rawr, w0z, c0z);
                gxn = fmaf(rawr, w0n, c0n);
            } else {
                gxr = rawr; gxz = rawz; gxn = rawn;
            }
            float r = sigm_fast(gxr + pgr + br);
            float z = sigm_fast(gxz + pgz + bz);
            float n = tanh_fast(fmaf(r, pgn + bn, gxn));
            float hn = fmaf(z, hreg - n, n);   // (1-z)*n + z*h
            hreg = hn;
            h_s[d][pr ^ 1][j] = hn;
            outp[(size_t)(t0 + s * tstep) * IN2H] = hn;
        }
        asm volatile("bar.sync %0, %1;" :: "r"(barid), "r"(128) : "memory");
    }
}

// ---------------- final FC on last timestep ----------------
__global__ void fc_kernel(const float* __restrict__ fc_w,
                          const float* __restrict__ fc_b,
                          float* __restrict__ out) {
    int b = blockIdx.x;
    int c = threadIdx.x;
    __shared__ float last[IN2H];
    if (threadIdx.x < IN2H)
        last[threadIdx.x] =
            g_buf[((size_t)b * Lseq + (Lseq - 1)) * IN2H + threadIdx.x];
    __syncthreads();
    if (c < NCLS) {
        float s = fc_b[c];
        const float* w = fc_w + (size_t)c * IN2H;
#pragma unroll 8
        for (int k = 0; k < IN2H; k++) s += last[k] * w[k];
        out[(size_t)b * NCLS + c] = s;
    }
}

extern "C" void kernel_launch(void* const* d_in, const int* in_sizes, int n_in,
                              void* d_out, int out_size) {
    const float* x     = (const float*)d_in[0];
    const float* w_ih0 = (const float*)d_in[1];
    const float* w_ih  = (const float*)d_in[2];
    const float* w_hh  = (const float*)d_in[3];
    const float* b_ih  = (const float*)d_in[4];
    const float* b_hh  = (const float*)d_in[5];
    const float* fc_w  = (const float*)d_in[6];
    const float* fc_b  = (const float*)d_in[7];
    float* out = (float*)d_out;

    // Layer 0: gx fused into the scan (input size 1)
    scan_kernel<<<Bsz, 256>>>(w_hh, b_hh, x, w_ih0, b_ih, 0);
    // Layers 1..3: GEMM input projection, then scan
    for (int l = 1; l < 4; l++) {
        gx_gemm_kernel<<<dim3(4, BL / 64), 256>>>(w_ih, b_ih, l);
        scan_kernel<<<Bsz, 256>>>(w_hh, b_hh, x, w_ih0, b_ih, l);
    }
    fc_kernel<<<Bsz, 256>>>(fc_w, fc_b, out);
}

// round 11
// speedup vs baseline: 2.0627x; 2.0627x over previous
#include <cuda_runtime.h>

#define Bsz   128
#define Lseq  4096
#define Hd    64
#define G3    192
#define IN2H  128
#define NCLS  230
#define BL    (Bsz * Lseq)

typedef unsigned long long ull;

// Scratch (allocation-free rule: __device__ globals)
__device__ float g_gx[(size_t)2 * BL * G3];    // [dir][b][t][192]  (~805 MB)
__device__ float g_buf[(size_t)BL * IN2H];     // [b][t][128]       (~268 MB)

// ---------------- packed f32x2 / fast-math helpers ----------------
__device__ __forceinline__ ull fma2(ull a, ull b, ull c) {
    ull d;
    asm("fma.rn.f32x2 %0, %1, %2, %3;" : "=l"(d) : "l"(a), "l"(b), "l"(c));
    return d;
}
__device__ __forceinline__ float2 u2f2(ull v) {
    float2 f;
    asm("mov.b64 {%0, %1}, %2;" : "=f"(f.x), "=f"(f.y) : "l"(v));
    return f;
}
__device__ __forceinline__ float tanh_fast(float x) {
    float y;
    asm("tanh.approx.f32 %0, %1;" : "=f"(y) : "f"(x));
    return y;
}
__device__ __forceinline__ float sigm_fast(float x) {
    return fmaf(0.5f, tanh_fast(0.5f * x), 0.5f);
}
__device__ __forceinline__ unsigned smem_u32(const void* p) {
    return (unsigned)__cvta_generic_to_shared(p);
}
__device__ __forceinline__ void cp_async8(unsigned dst, const void* src) {
    asm volatile("cp.async.ca.shared.global [%0], [%1], 8;"
                 :: "r"(dst), "l"(src));
}
__device__ __forceinline__ void cp_commit() {
    asm volatile("cp.async.commit_group;");
}
template <int N>
__device__ __forceinline__ void cp_wait() {
    asm volatile("cp.async.wait_group %0;" :: "n"(N));
}

// ---------------- gx GEMM for layers 1..3 (frozen R7 version) -------------
__global__ void __launch_bounds__(256, 2)
gx_gemm_kernel(const float* __restrict__ w_ih,
               const float* __restrict__ b_ih,
               int layer) {
    const int d  = blockIdx.x & 1;
    const int c0 = (blockIdx.x >> 1) * 96;       // column half
    const size_t row0 = (size_t)blockIdx.y * 64;
    const int tid = threadIdx.x;
    const int tx = tid & 15;   // cols c0 + tx + 16*j, j<6
    const int ty = tid >> 4;   // rows ty + 16*i, i<4

    const ull* inp2 = (const ull*)g_buf;  // 64 ull per row
    const ull* w2g =
        (const ull*)(w_ih + ((size_t)(layer - 1) * 2 + d) * G3 * IN2H);

    __shared__ ull a_s[2][16][65];   // [buf][kpair][row]
    __shared__ ull b_s[2][16][97];   // [buf][kpair][col]
    const unsigned A_BUF_BYTES = 16 * 65 * 8;
    const unsigned B_BUF_BYTES = 16 * 97 * 8;

    unsigned a_dst[4], b_dst[6];
    const ull* a_src[4];
    const ull* b_src[6];
#pragma unroll
    for (int it = 0; it < 4; it++) {
        int lin = tid + it * 256;
        int r = lin >> 4, c2 = lin & 15;
        a_dst[it] = smem_u32(&a_s[0][c2][r]);
        a_src[it] = inp2 + (row0 + r) * 64 + c2;
    }
#pragma unroll
    for (int it = 0; it < 6; it++) {
        int lin = tid + it * 256;
        int cc = lin >> 4, c2 = lin & 15;
        b_dst[it] = smem_u32(&b_s[0][c2][cc]);
        b_src[it] = w2g + (size_t)(c0 + cc) * 64 + c2;
    }

    ull acc[4][6];
#pragma unroll
    for (int i = 0; i < 4; i++)
#pragma unroll
        for (int j = 0; j < 6; j++) acc[i][j] = 0ULL;

#pragma unroll
    for (int it = 0; it < 4; it++) cp_async8(a_dst[it], a_src[it]);
#pragma unroll
    for (int it = 0; it < 6; it++) cp_async8(b_dst[it], b_src[it]);
    cp_commit();

#pragma unroll
    for (int ch = 0; ch < 4; ch++) {
        const int buf = ch & 1;
        if (ch < 3) {
            const int nb = (ch + 1) & 1;
#pragma unroll
            for (int it = 0; it < 4; it++)
                cp_async8(a_dst[it] + nb * A_BUF_BYTES,
                          a_src[it] + (ch + 1) * 16);
#pragma unroll
            for (int it = 0; it < 6; it++)
                cp_async8(b_dst[it] + nb * B_BUF_BYTES,
                          b_src[it] + (ch + 1) * 16);
            cp_commit();
            cp_wait<1>();
        } else {
            cp_wait<0>();
        }
        __syncthreads();
#pragma unroll
        for (int kp = 0; kp < 16; kp++) {
            ull a2[4], b2[6];
#pragma unroll
            for (int i = 0; i < 4; i++) a2[i] = a_s[buf][kp][ty + 16 * i];
#pragma unroll
            for (int j = 0; j < 6; j++) b2[j] = b_s[buf][kp][tx + 16 * j];
#pragma unroll
            for (int i = 0; i < 4; i++)
#pragma unroll
                for (int j = 0; j < 6; j++)
                    acc[i][j] = fma2(a2[i], b2[j], acc[i][j]);
        }
        __syncthreads();
    }

    const float* bih = b_ih + ((size_t)layer * 2 + d) * G3;
#pragma unroll
    for (int i = 0; i < 4; i++) {
        size_t row = row0 + ty + 16 * i;
#pragma unroll
        for (int j = 0; j < 6; j++) {
            int c = c0 + tx + 16 * j;
            float2 f = u2f2(acc[i][j]);
            g_gx[((size_t)d * BL + row) * G3 + c] = f.x + f.y + bih[c];
        }
    }
}

// ---------------- sequential GRU scan (split-k + shuffle, NO dynamic idx) --
// One block per batch element, 256 threads. tid = d*128 + j*2 + half:
//   d    = direction (two independent 128-thread groups, named barriers)
//   j    = h-component 0..63
//   half = which 32-wide k-half of the dots this thread computes
// Each thread computes ALL THREE gate dots (r,z,n) for component j over its
// k-half (weights 3x16 ull = 96 regs). Halves combine via shfl_xor(1).
// Ping-pong h buffer; step loop unrolled x2 so the parity is a COMPILE-TIME
// constant (R10's dynamic ring index demoted q[] to local memory).
__global__ void __launch_bounds__(256)
scan_kernel(const float* __restrict__ w_hh,
            const float* __restrict__ b_hh,
            const float* __restrict__ x,
            const float* __restrict__ w_ih0,
            const float* __restrict__ b_ih,
            int layer) {
    const int b = blockIdx.x;
    const int tid = threadIdx.x;
    const int d = tid >> 7;            // direction
    const int j = (tid & 127) >> 1;    // component
    const int half = tid & 1;          // k-half
    const unsigned barid = 1 + d;

    const size_t base = ((size_t)layer * 2 + d) * G3;
    const ull* Wr = (const ull*)w_hh + (base + j) * 32 + half * 16;
    const ull* Wz = (const ull*)w_hh + (base + 64 + j) * 32 + half * 16;
    const ull* Wn = (const ull*)w_hh + (base + 128 + j) * 32 + half * 16;
    ull wr[16], wz[16], wn[16];
#pragma unroll
    for (int i = 0; i < 16; i++) { wr[i] = Wr[i]; wz[i] = Wz[i]; wn[i] = Wn[i]; }
    const float br = b_hh[base + j];
    const float bz = b_hh[base + 64 + j];
    const float bn = b_hh[base + 128 + j];

    __shared__ __align__(16) float h_s[2][2][Hd];  // [dir][parity][comp]
    if ((tid & 127) < Hd) h_s[d][0][tid & 127] = 0.0f;
    float hreg = 0.0f;  // previous h[j], maintained on half==0

    const int t0 = (d == 0) ? 0 : (Lseq - 1);
    const int tstep = (d == 0) ? 1 : -1;
    const long gstep = (long)tstep * G3;

    // gx feed — only half==0 threads consume it
    float w0r = 0.f, w0z = 0.f, w0n = 0.f, c0r = 0.f, c0z = 0.f, c0n = 0.f;
    const float* xs = nullptr;
    const float* gp = nullptr;
    if (layer == 0) {
        w0r = w_ih0[d * G3 + j];
        w0z = w_ih0[d * G3 + 64 + j];
        w0n = w_ih0[d * G3 + 128 + j];
        c0r = b_ih[(size_t)d * G3 + j];
        c0z = b_ih[(size_t)d * G3 + 64 + j];
        c0n = b_ih[(size_t)d * G3 + 128 + j];
        xs = x + (size_t)b * Lseq + t0;
    } else {
        gp = g_gx + (((size_t)d * Bsz + b) * Lseq + t0) * G3 + j;
    }
    float* outp = g_buf + (size_t)b * Lseq * IN2H + d * Hd + j;

    asm volatile("bar.sync %0, %1;" :: "r"(barid), "r"(128) : "memory");

    // depth-2 prefetch as STATIC scalars (parity 0 / parity 1)
    float qr0 = 0.f, qz0 = 0.f, qn0 = 0.f;
    float qr1 = 0.f, qz1 = 0.f, qn1 = 0.f;
    if (half == 0) {
        if (layer == 0) {
            qr0 = xs[0];
            qr1 = xs[(long)tstep];
        } else {
            qr0 = gp[0];        qz0 = gp[64];        qn0 = gp[128];
            qr1 = gp[gstep];    qz1 = gp[gstep + 64]; qn1 = gp[gstep + 128];
        }
    }

#define SCAN_STEP(PR, S)                                                      \
    {                                                                         \
        const int s_ = (S);                                                   \
        float rawr = qr##PR, rawz = qz##PR, rawn = qn##PR;                    \
        const int sp_ = s_ + 2;                                               \
        if (half == 0 && sp_ < Lseq) {                                        \
            if (layer == 0) {                                                 \
                qr##PR = xs[(long)sp_ * tstep];                               \
            } else {                                                          \
                qr##PR = gp[(long)sp_ * gstep];                               \
                qz##PR = gp[(long)sp_ * gstep + 64];                          \
                qn##PR = gp[(long)sp_ * gstep + 128];                         \
            }                                                                 \
        }                                                                     \
        const ulonglong2* h4_ =                                               \
            (const ulonglong2*)(h_s[d][PR] + half * 32);                      \
        ull r0 = 0, r1 = 0, z0 = 0, z1 = 0, n0 = 0, n1 = 0;                   \
        _Pragma("unroll")                                                     \
        for (int i = 0; i < 4; i++) {                                         \
            ulonglong2 u = h4_[2 * i];                                        \
            ulonglong2 v = h4_[2 * i + 1];                                    \
            r0 = fma2(wr[4 * i + 0], u.x, r0);                                \
            r1 = fma2(wr[4 * i + 1], u.y, r1);                                \
            z0 = fma2(wz[4 * i + 0], u.x, z0);                                \
            z1 = fma2(wz[4 * i + 1], u.y, z1);                                \
            n0 = fma2(wn[4 * i + 0], u.x, n0);                                \
            n1 = fma2(wn[4 * i + 1], u.y, n1);                                \
            r0 = fma2(wr[4 * i + 2], v.x, r0);                                \
            r1 = fma2(wr[4 * i + 3], v.y, r1);                                \
            z0 = fma2(wz[4 * i + 2], v.x, z0);                                \
            z1 = fma2(wz[4 * i + 3], v.y, z1);                                \
            n0 = fma2(wn[4 * i + 2], v.x, n0);                                \
            n1 = fma2(wn[4 * i + 3], v.y, n1);                                \
        }                                                                     \
        float2 fr0 = u2f2(r0), fr1 = u2f2(r1);                                \
        float2 fz0 = u2f2(z0), fz1 = u2f2(z1);                                \
        float2 fn0 = u2f2(n0), fn1 = u2f2(n1);                                \
        float pgr = (fr0.x + fr0.y) + (fr1.x + fr1.y);                        \
        float pgz = (fz0.x + fz0.y) + (fz1.x + fz1.y);                        \
        float pgn = (fn0.x + fn0.y) + (fn1.x + fn1.y);                        \
        pgr += __shfl_xor_sync(0xFFFFFFFFu, pgr, 1);                          \
        pgz += __shfl_xor_sync(0xFFFFFFFFu, pgz, 1);                          \
        pgn += __shfl_xor_sync(0xFFFFFFFFu, pgn, 1);                          \
        if (half == 0) {                                                      \
            float gxr, gxz, gxn;                                              \
            if (layer == 0) {                                                 \
                gxr = fmaf(rawr, w0r, c0r);                                   \
                gxz = fmaf(rawr, w0z, c0z);                                   \
                gxn = fmaf(rawr, w0n, c0n);                                   \
            } else {                                                          \
                gxr = rawr; gxz = rawz; gxn = rawn;                           \
            }                                                                 \
            float r_ = sigm_fast(gxr + pgr + br);                             \
            float z_ = sigm_fast(gxz + pgz + bz);                             \
            float n_ = tanh_fast(fmaf(r_, pgn + bn, gxn));                    \
            float hn = fmaf(z_, hreg - n_, n_);                               \
            hreg = hn;                                                        \
            h_s[d][1 - (PR)][j] = hn;                                         \
            outp[(size_t)(t0 + s_ * tstep) * IN2H] = hn;                      \
        }                                                                     \
        asm volatile("bar.sync %0, %1;" :: "r"(barid), "r"(128) : "memory");  \
    }

#pragma unroll 1
    for (int s0 = 0; s0 < Lseq; s0 += 2) {
        SCAN_STEP(0, s0)
        SCAN_STEP(1, s0 + 1)
    }
#undef SCAN_STEP
}

// ---------------- final FC on last timestep ----------------
__global__ void fc_kernel(const float* __restrict__ fc_w,
                          const float* __restrict__ fc_b,
                          float* __restrict__ out) {
    int b = blockIdx.x;
    int c = threadIdx.x;
    __shared__ float last[IN2H];
    if (threadIdx.x < IN2H)
        last[threadIdx.x] =
            g_buf[((size_t)b * Lseq + (Lseq - 1)) * IN2H + threadIdx.x];
    __syncthreads();
    if (c < NCLS) {
        float s = fc_b[c];
        const float* w = fc_w + (size_t)c * IN2H;
#pragma unroll 8
        for (int k = 0; k < IN2H; k++) s += last[k] * w[k];
        out[(size_t)b * NCLS + c] = s;
    }
}

extern "C" void kernel_launch(void* const* d_in, const int* in_sizes, int n_in,
                              void* d_out, int out_size) {
    const float* x     = (const float*)d_in[0];
    const float* w_ih0 = (const float*)d_in[1];
    const float* w_ih  = (const float*)d_in[2];
    const float* w_hh  = (const float*)d_in[3];
    const float* b_ih  = (const float*)d_in[4];
    const float* b_hh  = (const float*)d_in[5];
    const float* fc_w  = (const float*)d_in[6];
    const float* fc_b  = (const float*)d_in[7];
    float* out = (float*)d_out;

    // Layer 0: gx fused into the scan (input size 1)
    scan_kernel<<<Bsz, 256>>>(w_hh, b_hh, x, w_ih0, b_ih, 0);
    // Layers 1..3: GEMM input projection, then scan
    for (int l = 1; l < 4; l++) {
        gx_gemm_kernel<<<dim3(4, BL / 64), 256>>>(w_ih, b_ih, l);
        scan_kernel<<<Bsz, 256>>>(w_hh, b_hh, x, w_ih0, b_ih, l);
    }
    fc_kernel<<<Bsz, 256>>>(fc_w, fc_b, out);
}